// round 6
// baseline (speedup 1.0000x reference)
#include <cuda_runtime.h>
#include <cuda_bf16.h>
#include <cstdint>

// out = (v_reset > 0.5) with v_reset = v*(1-spike1) provably <= 0.5 always
// -> output identically ZERO for all inputs -> pure 134MB zero-fill.
//
// History:
//  R1: 1x16B STG/thread        dur 23.14  (6.65 TB/s)
//  R2: 8x16B + .cs             NEUTRAL
//  R4: 134MB evict_last        31.2us REGRESSED (footprint > 126MB L2 ->
//      policy thrash)
//  R5: graph memset node       dur 23.01  NEUTRAL -> CE path hits the same
//      ~6.65 TB/s ceiling => binder is DRAM write bandwidth, not LTS.
//
// R6: SPLIT RESIDENCY. Pin 96MB (< L2 capacity) with L2::evict_last ->
// steady-state graph replays write-hit resident dirty lines, zero DRAM
// writeback for that region. Stream the remaining 38MB with .cs
// (evict-first) so it can't displace the pinned set. Steady state:
// time = max(134MB/LTS_bw(~9.5TB/s), 38MB/DRAM_wr(~6.65TB/s)) ~ 14us kernel.

#define ST_PER_THREAD 8            // 8 x 32B = 256B per thread
#define GROUPS_PER_BLOCK (256 * ST_PER_THREAD)   // 2048 x 32B = 64KB / block
#define RESIDENT_BLOCKS 1536       // 1536 * 64KB = 96MB pinned in L2

__global__ void __launch_bounds__(256) zero_fill_split(float* __restrict__ out,
                                                       long long n8) {
    long long base = (long long)blockIdx.x * GROUPS_PER_BLOCK + threadIdx.x;
    if (blockIdx.x < RESIDENT_BLOCKS) {
        // L2-resident region: 256-bit evict_last stores
#pragma unroll
        for (int k = 0; k < ST_PER_THREAD; k++) {
            long long i = base + (long long)k * 256;
            if (i < n8) {
                float* p = out + i * 8;
                asm volatile(
                    "st.global.L2::evict_last.v8.f32 [%0], "
                    "{%1, %2, %3, %4, %5, %6, %7, %8};"
                    :: "l"(p),
                       "f"(0.0f), "f"(0.0f), "f"(0.0f), "f"(0.0f),
                       "f"(0.0f), "f"(0.0f), "f"(0.0f), "f"(0.0f)
                    : "memory");
            }
        }
    } else {
        // Streaming region: evict-first so it never displaces the pinned set
        const float4 z = make_float4(0.f, 0.f, 0.f, 0.f);
#pragma unroll
        for (int k = 0; k < ST_PER_THREAD; k++) {
            long long i = base + (long long)k * 256;
            if (i < n8) {
                float4* p = (float4*)(out + i * 8);
                __stcs(p + 0, z);
                __stcs(p + 1, z);
            }
        }
    }
}

__global__ void zero_fill_tail(float* __restrict__ out,
                               long long start, long long n) {
    long long i = start + (long long)blockIdx.x * blockDim.x + threadIdx.x;
    if (i < n) out[i] = 0.f;
}

extern "C" void kernel_launch(void* const* d_in, const int* in_sizes, int n_in,
                              void* d_out, int out_size) {
    (void)d_in; (void)in_sizes; (void)n_in;

    long long n = (long long)out_size;   // 33,554,432 floats (134MB)
    long long n8 = n / 8;                // 4,194,304 32B groups

    long long blocks = (n8 + GROUPS_PER_BLOCK - 1) / GROUPS_PER_BLOCK; // 2048
    if (blocks > 0) {
        zero_fill_split<<<(unsigned)blocks, 256>>>((float*)d_out, n8);
    }

    long long rem_start = n8 * 8;
    if (n - rem_start > 0) {
        zero_fill_tail<<<1, 256>>>((float*)d_out, rem_start, n);
    }
}

// round 7
// speedup vs baseline: 1.1383x; 1.1383x over previous
#include <cuda_runtime.h>
#include <cuda_bf16.h>
#include <cstdint>

// out = (v_reset > 0.5) with v_reset = v*(1-spike1) provably <= 0.5 always
// -> output identically ZERO for all inputs -> pure 134MB zero-fill.
//
// History:
//  R1: SM 16B stores            dur 23.14   (6.65 TB/s)
//  R2: SM 8x16B + .cs           NEUTRAL
//  R4: 134MB evict_last         31.2us REGRESS
//  R5: CE memset node           dur 23.01   (same 6.65 TB/s ceiling)
//  R6: 96MB evict_last + .cs    27.4us REGRESS (evict_last path is slow
//      at ANY footprint; L2-residency schemes closed)
//
// R7: CONCURRENT SM + CE. First half via SM kernel on the capture stream,
// second half via CE memset on a forked non-blocking stream (event
// fork/join -> both captured into the graph as parallel branches).
// Discriminates shared-DRAM ceiling (neutral ~23us) vs per-path caps
// (win ~13.5us). kernel_launch runs only twice (correctness + capture),
// so leaking the stream/events is bounded; no device allocation.

__global__ void __launch_bounds__(256) zero_fill_v4(float4* __restrict__ out,
                                                    long long n4) {
    long long i = (long long)blockIdx.x * blockDim.x + threadIdx.x;
    if (i < n4) {
        out[i] = make_float4(0.f, 0.f, 0.f, 0.f);
    }
}

__global__ void zero_fill_tail(float* __restrict__ out,
                               long long start, long long n) {
    long long i = start + (long long)blockIdx.x * blockDim.x + threadIdx.x;
    if (i < n) out[i] = 0.f;
}

extern "C" void kernel_launch(void* const* d_in, const int* in_sizes, int n_in,
                              void* d_out, int out_size) {
    (void)d_in; (void)in_sizes; (void)n_in;

    float* out = (float*)d_out;
    long long n = (long long)out_size;          // 33,554,432 floats (134MB)

    // Split: first half -> SM kernel, second half -> CE memset (concurrent).
    long long half = (n / 2) & ~15LL;           // 16-float aligned split
    long long n4_first = half / 4;              // float4 count, first half
    size_t bytes_second = (size_t)(n - half) * sizeof(float);

    // Fork a non-blocking stream off the capture stream.
    cudaStream_t s2;
    cudaEvent_t ev_fork, ev_join;
    bool forked = (cudaStreamCreateWithFlags(&s2, cudaStreamNonBlocking) == cudaSuccess)
               && (cudaEventCreateWithFlags(&ev_fork, cudaEventDisableTiming) == cudaSuccess)
               && (cudaEventCreateWithFlags(&ev_join, cudaEventDisableTiming) == cudaSuccess);

    if (forked) {
        cudaEventRecord(ev_fork, 0);
        cudaStreamWaitEvent(s2, ev_fork, 0);
        // CE branch: second half
        cudaMemsetAsync(out + half, 0, bytes_second, s2);
        cudaEventRecord(ev_join, s2);

        // SM branch: first half, concurrent on the capture stream
        const int threads = 256;
        long long blocks = (n4_first + threads - 1) / threads;
        if (blocks > 0)
            zero_fill_v4<<<(unsigned)blocks, threads>>>((float4*)out, n4_first);

        // Join CE branch back into the capture stream.
        cudaStreamWaitEvent(0, ev_join, 0);
        // Intentionally not destroying s2/events mid-capture; kernel_launch
        // is called only for the correctness run and the capture call.
    } else {
        // Fallback: single memset (R5 behavior, 23.0us)
        cudaMemsetAsync(out, 0, (size_t)n * sizeof(float), 0);
        return;
    }

    // Tail safety (n divisible by 16 for the real shape; never fires there)
    long long covered = half + (long long)(bytes_second / sizeof(float));
    if (covered < n)
        zero_fill_tail<<<1, 256>>>(out, covered, n);
}

// round 8
// speedup vs baseline: 1.1905x; 1.0459x over previous
#include <cuda_runtime.h>
#include <cuda_bf16.h>
#include <cstdint>

// OutputLayer LIF step — algebraic identity: out = (v_reset > 0.5) where
// v_reset = v*(1-spike1). If v > thr it resets to exactly 0; otherwise
// v <= thr and the final compare is strict. So out == 0 for ALL inputs,
// and the optimal kernel is a pure 134MB zero-fill of d_out.
//
// Optimization history (GB300, sm_103a):
//  R1: SM 16B stores            dur 23.14   (6.65 TB/s)
//  R2: SM 8x16B + .cs hint      NEUTRAL     (not issue/wave bound)
//  R4: 134MB evict_last         31.2us      REGRESS (policy thrash)
//  R5: single CE memset node    dur 23.01   BEST
//  R6: 96MB evict_last split    27.4us      REGRESS (evict_last path slow
//                                           at any footprint)
//  R7: concurrent SM + CE       dur 24.06   NEUTRAL-minus => the 6.65 TB/s
//      ceiling is a SHARED DRAM-write cap, not per-path.
//
// Converged model: floor = 134MB / 6.65TB/s (~20.2us engine) + ~2.8us
// per-replay graph overhead => ~23.0us. Steady-state L2 reuse is
// impossible (sequential-scan LRU thrash; evict_last path regresses), and
// multi-engine concurrency cannot exceed the shared DRAM ceiling.
// => Single memset node is floor-optimal. Locking it in.

extern "C" void kernel_launch(void* const* d_in, const int* in_sizes, int n_in,
                              void* d_out, int out_size) {
    (void)d_in; (void)in_sizes; (void)n_in;

    size_t bytes = (size_t)out_size * sizeof(float);   // 134,217,728 bytes
    // Single memset node on the capture (default) stream: one graph node,
    // CE fill path, DRAM-write bound.
    cudaMemsetAsync(d_out, 0, bytes, 0);
}